// round 13
// baseline (speedup 1.0000x reference)
#include <cuda_runtime.h>
#include <cuda_fp16.h>
#include <math.h>
#include <cstdint>

// Problem constants
#define B_ 4
#define T_ 2048
#define C_ 1024
#define H_ 16
#define D_ 64
#define BT_ (B_ * T_)           // 8192

// Scratch (fp16 end-to-end; fp32 only in accumulators and final out)
__device__ __half g_q[B_ * H_ * T_ * D_];    // [B,H,T,D], pre-scaled by 0.125*log2e
__device__ __half g_k[B_ * H_ * T_ * D_];    // [B,H,T,D]
__device__ __half g_vt[B_ * H_ * D_ * T_];   // [B,H,D,T]  (V transposed)
__device__ __half g_att[B_ * T_ * C_];       // [B,T,H*D]
__device__ __half g_wt[3 * C_ * C_];         // K-major qkv weights [n=3072][k=1024]
__device__ __half g_wot[C_ * C_];            // K-major Wo [n=1024][k=1024]
__device__ __half g_xh[BT_ * C_];            // fp16 x

// Q pre-scale: (1/sqrt(64)) * log2(e), so softmax can use exp2 directly.
#define QSCALE 0.18033688011112042f

// ===========================================================================
// Helpers
// ===========================================================================
__device__ __forceinline__ void mma_fp16(float* c, const uint32_t* a, const uint32_t* b) {
    asm volatile(
        "mma.sync.aligned.m16n8k16.row.col.f32.f16.f16.f32 "
        "{%0,%1,%2,%3}, {%4,%5,%6,%7}, {%8,%9}, {%0,%1,%2,%3};\n"
        : "+f"(c[0]), "+f"(c[1]), "+f"(c[2]), "+f"(c[3])
        : "r"(a[0]), "r"(a[1]), "r"(a[2]), "r"(a[3]),
          "r"(b[0]), "r"(b[1]));
}

__device__ __forceinline__ void ldmx4(uint32_t* d, uint32_t addr) {
    asm volatile("ldmatrix.sync.aligned.m8n8.x4.shared.b16 {%0,%1,%2,%3}, [%4];"
        : "=r"(d[0]), "=r"(d[1]), "=r"(d[2]), "=r"(d[3]) : "r"(addr));
}

__device__ __forceinline__ uint32_t smem_u32(const void* p) {
    return (uint32_t)__cvta_generic_to_shared(p);
}

__device__ __forceinline__ uint32_t pack_h2(float lo, float hi) {
    __half2 h = __halves2half2(__float2half_rn(lo), __float2half_rn(hi));
    return *reinterpret_cast<uint32_t*>(&h);
}

#define CPA16(dst, src) \
    asm volatile("cp.async.ca.shared.global [%0], [%1], 16;" :: "r"(dst), "l"(src))
#define CP_COMMIT() asm volatile("cp.async.commit_group;" ::: "memory")
#define CP_WAIT0()  asm volatile("cp.async.wait_group 0;" ::: "memory")

extern __shared__ __align__(16) __half dyn_smh[];

// ===========================================================================
// Dense GEMM (fp16): 256 threads / 8 warps, warp tile 64x32 (2x4 layout),
// block 128x128x64.  2-stage cp.async; ldmatrix fragments.
// SMEM row stride 72 halves (row r starts at bank 4r%32 -> ldmatrix CF).
// 4 warps/SMSP at 2 CTAs/SM hides per-chunk barrier/scoreboard stalls.
// ===========================================================================
#define HSTR 72
#define TILEH (128 * HSTR)                 // 9216 halves
#define BUFH  (2 * TILEH)                  // A+B per stage
#define GEMM_SMEM_BYTES (2 * BUFH * 2)     // 73728 bytes

__device__ __forceinline__ void gemm_issue_chunk(
    const __half* __restrict__ A0, const __half* __restrict__ B0,
    uint32_t sb32, int kc, int buf, int pr, int pc8)
{
    const uint32_t abase = sb32 + (uint32_t)(buf * BUFH) * 2;
    const uint32_t bbase = abase + (uint32_t)TILEH * 2;
    #pragma unroll
    for (int l = 0; l < 4; l++) {
        const int r = pr + l * 32;
        const uint32_t so = (uint32_t)(r * HSTR + pc8 * 8) * 2;
        CPA16(abase + so, A0 + (size_t)r * C_ + kc * 64 + pc8 * 8);
        CPA16(bbase + so, B0 + (size_t)r * C_ + kc * 64 + pc8 * 8);
    }
}

__device__ __forceinline__ void gemm_mainloop_fp16(
    const __half* __restrict__ A0, const __half* __restrict__ B0,
    float c[4][4][4])
{
    const int tid  = threadIdx.x;
    const int lane = tid & 31;
    const int wid  = tid >> 5;           // 0..7
    const int wm = (wid & 1) * 64;
    const int wn = (wid >> 1) * 32;
    const int l8 = lane & 7;
    const int mi = lane >> 3;            // ldmatrix sub-matrix index 0..3
    const int arow = (mi & 1) * 8;
    const int acol = (mi >> 1) * 8;
    const int brow = (mi >> 1) * 8;
    const int bcol = (mi & 1) * 8;
    const int pc8 = tid & 7;
    const int pr  = tid >> 3;            // 0..31

    const uint32_t sb32 = smem_u32(dyn_smh);

    #pragma unroll
    for (int mf = 0; mf < 4; mf++)
        #pragma unroll
        for (int nf = 0; nf < 4; nf++)
            #pragma unroll
            for (int r = 0; r < 4; r++) c[mf][nf][r] = 0.0f;

    gemm_issue_chunk(A0, B0, sb32, 0, 0, pr, pc8);
    CP_COMMIT();

    for (int kc = 0; kc < 16; kc++) {
        const int buf = kc & 1;
        CP_WAIT0();
        __syncthreads();
        if (kc < 15) {
            gemm_issue_chunk(A0, B0, sb32, kc + 1, buf ^ 1, pr, pc8);
            CP_COMMIT();
        }

        const uint32_t sA32 = sb32 + (uint32_t)(buf * BUFH) * 2;
        const uint32_t sB32 = sA32 + (uint32_t)TILEH * 2;

        #pragma unroll
        for (int ks = 0; ks < 4; ks++) {
            const int k0 = ks * 16;
            uint32_t a[4][4];
            #pragma unroll
            for (int mf = 0; mf < 4; mf++)
                ldmx4(a[mf], sA32 +
                      (uint32_t)((wm + mf * 16 + l8 + arow) * HSTR + k0 + acol) * 2);
            uint32_t b[2][4];    // pair p covers nf=2p, 2p+1
            #pragma unroll
            for (int p = 0; p < 2; p++)
                ldmx4(b[p], sB32 +
                      (uint32_t)((wn + p * 16 + l8 + brow) * HSTR + k0 + bcol) * 2);
            #pragma unroll
            for (int mf = 0; mf < 4; mf++)
                #pragma unroll
                for (int nf = 0; nf < 4; nf++)
                    mma_fp16(c[mf][nf], a[mf], &b[nf >> 1][(nf & 1) * 2]);
        }
    }
}

// ===========================================================================
// Merged prep kernel: convert x + transpose qkv weights + transpose Wo.
// grid.x = 4096 + 3072 + 1024 = 8192 blocks of 256 threads.
// ===========================================================================
__global__ __launch_bounds__(256) void prep_all(
    const float* __restrict__ x,
    const float* __restrict__ Wq, const float* __restrict__ Wk,
    const float* __restrict__ Wv, const float* __restrict__ Wo)
{
    __shared__ float tile[32][33];
    const int bid = blockIdx.x;

    if (bid < 4096) {
        // convert x -> fp16
        const int base = (bid * 256 + threadIdx.x) * 8;
        float4 v0 = *(const float4*)(x + base);
        float4 v1 = *(const float4*)(x + base + 4);
        uint4 o;
        o.x = pack_h2(v0.x, v0.y);
        o.y = pack_h2(v0.z, v0.w);
        o.z = pack_h2(v1.x, v1.y);
        o.w = pack_h2(v1.z, v1.w);
        *(uint4*)(g_xh + base) = o;
        return;
    }

    const int tx = threadIdx.x & 31, ty = threadIdx.x >> 5;

    if (bid < 7168) {
        // transpose qkv weights (orig grid 32 x 2 x 48)
        const int idx = bid - 4096;
        const int z = idx >> 6;             // 0..47
        const int rem = idx & 63;
        const int c0 = (rem & 31) * 32;
        const int d0 = (rem >> 5) * 32;
        const int which = z >> 4, h = z & 15;
        const float* W = (which == 0 ? Wq : (which == 1 ? Wk : Wv)) + (size_t)h * C_ * D_;

        #pragma unroll
        for (int i = 0; i < 4; i++)
            tile[ty + i * 8][tx] = W[(size_t)(c0 + ty + i * 8) * D_ + d0 + tx];
        __syncthreads();
        const int nbase = which * 1024 + h * 64 + d0;
        #pragma unroll
        for (int i = 0; i < 4; i++)
            g_wt[(size_t)(nbase + ty + i * 8) * C_ + c0 + tx] =
                __float2half_rn(tile[tx][ty + i * 8]);
    } else {
        // transpose Wo (orig grid 32 x 32)
        const int idx = bid - 7168;
        const int c0 = (idx & 31) * 32;
        const int n0 = (idx >> 5) * 32;
        #pragma unroll
        for (int i = 0; i < 4; i++)
            tile[ty + i * 8][tx] = Wo[(size_t)(c0 + ty + i * 8) * C_ + n0 + tx];
        __syncthreads();
        #pragma unroll
        for (int i = 0; i < 4; i++)
            g_wot[(size_t)(n0 + ty + i * 8) * C_ + c0 + tx] =
                __float2half_rn(tile[tx][ty + i * 8]);
    }
}

// ===========================================================================
// Kernel 1: QKV projection (fp16).  grid (64, 24), 256 threads.
// ===========================================================================
__global__ __launch_bounds__(256, 2) void qkv_tc()
{
    const int mt = blockIdx.x, nt = blockIdx.y;
    const __half* A0 = g_xh + (size_t)mt * 128 * C_;
    const __half* B0 = g_wt + (size_t)nt * 128 * C_;

    float c[4][4][4];
    gemm_mainloop_fp16(A0, B0, c);

    const int tid  = threadIdx.x;
    const int lane = tid & 31;
    const int wid  = tid >> 5;
    const int wm = (wid & 1) * 64;
    const int wn = (wid >> 1) * 32;
    const int g = lane >> 2;
    const int t4 = lane & 3;

    const int nb0 = nt * 128 + wn;
    const int which = nb0 >> 10;
    const int hh = (nb0 >> 6) & 15;
    const int dbase = nb0 & 63;          // 0 or 32 within the head

    if (which == 2) {
        // V: write transposed [B,H,D,T] as u16 scatters
        #pragma unroll
        for (int mf = 0; mf < 4; mf++) {
            #pragma unroll
            for (int half = 0; half < 2; half++) {
                const int m = mt * 128 + wm + mf * 16 + g + half * 8;
                const int b = m >> 11, tt = m & (T_ - 1);
                __half* vb = g_vt + ((size_t)(b * H_ + hh) * D_) * T_;
                #pragma unroll
                for (int nf = 0; nf < 4; nf++) {
                    const int d = dbase + nf * 8 + t4 * 2;
                    const float cv0 = c[mf][nf][half * 2 + 0];
                    const float cv1 = c[mf][nf][half * 2 + 1];
                    vb[(size_t)d * T_ + tt]       = __float2half_rn(cv0);
                    vb[(size_t)(d + 1) * T_ + tt] = __float2half_rn(cv1);
                }
            }
        }
    } else {
        const float sc = (which == 0) ? QSCALE : 1.0f;
        __half* outb = (which == 0 ? g_q : g_k);
        #pragma unroll
        for (int mf = 0; mf < 4; mf++) {
            #pragma unroll
            for (int half = 0; half < 2; half++) {
                const int m = mt * 128 + wm + mf * 16 + g + half * 8;
                const int b = m >> 11, tt = m & (T_ - 1);
                __half* op = outb + ((size_t)(b * H_ + hh) * T_ + tt) * D_;
                #pragma unroll
                for (int nf = 0; nf < 4; nf++) {
                    const int d = dbase + nf * 8 + t4 * 2;
                    *(uint32_t*)(op + d) = pack_h2(c[mf][nf][half * 2] * sc,
                                                   c[mf][nf][half * 2 + 1] * sc);
                }
            }
        }
    }
}

// ===========================================================================
// Kernel 3: output projection + bias (fp16 in, fp32 out).  grid (64, 8).
// ===========================================================================
__global__ __launch_bounds__(256, 2) void proj_tc(float* __restrict__ out,
                                                  const float* __restrict__ bo)
{
    const int mt = blockIdx.x, nt = blockIdx.y;
    const __half* A0 = g_att + (size_t)mt * 128 * C_;
    const __half* B0 = g_wot + (size_t)nt * 128 * C_;

    float c[4][4][4];
    gemm_mainloop_fp16(A0, B0, c);

    const int tid  = threadIdx.x;
    const int lane = tid & 31;
    const int wid  = tid >> 5;
    const int wm = (wid & 1) * 64;
    const int wn = (wid >> 1) * 32;
    const int g = lane >> 2;
    const int t4 = lane & 3;

    #pragma unroll
    for (int mf = 0; mf < 4; mf++) {
        #pragma unroll
        for (int half = 0; half < 2; half++) {
            const int m = mt * 128 + wm + mf * 16 + g + half * 8;
            #pragma unroll
            for (int nf = 0; nf < 4; nf++) {
                const int n = nt * 128 + wn + nf * 8 + t4 * 2;
                float2 bv = *(const float2*)(bo + n);
                float2 v = make_float2(c[mf][nf][half * 2] + bv.x,
                                       c[mf][nf][half * 2 + 1] + bv.y);
                *(float2*)(out + (size_t)m * C_ + n) = v;
            }
        }
    }
}

// ===========================================================================
// Kernel 2: fp16 tensor-core causal flash attention (ldmatrix fragments).
// BQ=128, BS=64, 256 threads.  Q/P share one SMEM region (warp-private rows).
// Work-descending qb order; exp2-domain softmax; fully-masked warp tiles skip;
// deferred (per-lane) l-sum reduction.
// ===========================================================================
#define AQP 0                        // Q then P: 128 x 72 halves
#define AKS (128 * HSTR)             // 9216
#define AKB (64 * HSTR)              // 4608
#define AVS (AKS + 2 * AKB)          // 18432
#define AVB (64 * HSTR)
#define ATTN_SMEM_BYTES ((AVS + 2 * AVB) * 2)   // 55296 bytes

__device__ __forceinline__ void attn_issue_kv(
    const __half* __restrict__ kp, const __half* __restrict__ vtp,
    uint32_t sb32, int sb, int buf, int tid)
{
    const uint32_t kdst = sb32 + (uint32_t)(AKS + buf * AKB) * 2;
    const uint32_t vdst = sb32 + (uint32_t)(AVS + buf * AVB) * 2;
    #pragma unroll
    for (int l = 0; l < 2; l++) {
        const int idx = tid + l * 256;   // 0..511
        const int r = idx >> 3, c8 = idx & 7;
        CPA16(kdst + (uint32_t)(r * HSTR + c8 * 8) * 2,
              kp + (size_t)(sb * 64 + r) * D_ + c8 * 8);
        CPA16(vdst + (uint32_t)(r * HSTR + c8 * 8) * 2,
              vtp + (size_t)r * T_ + sb * 64 + c8 * 8);
    }
}

__global__ __launch_bounds__(256, 2) void attn_mma_kernel()
{
    __half* sfh = dyn_smh;
    const int tid  = threadIdx.x;
    const int lane = tid & 31;
    const int w    = tid >> 5;
    const int g    = lane >> 2;
    const int t    = lane & 3;
    const int l8   = lane & 7;
    const int mi   = lane >> 3;
    const int arow = (mi & 1) * 8;
    const int acol = (mi >> 1) * 8;
    const int brow = (mi >> 1) * 8;
    const int bcol = (mi & 1) * 8;
    const int qb   = (int)gridDim.x - 1 - (int)blockIdx.x;  // heavy blocks first
    const int bh   = blockIdx.y;        // 0..63

    const __half* qp  = g_q  + (size_t)bh * T_ * D_;
    const __half* kp  = g_k  + (size_t)bh * T_ * D_;
    const __half* vtp = g_vt + (size_t)bh * D_ * T_;
    const uint32_t sb32 = smem_u32(sfh);

    // stage Q (already QSCALE-scaled) + K/V(0) via cp.async
    attn_issue_kv(kp, vtp, sb32, 0, 0, tid);
    #pragma unroll
    for (int l = 0; l < 4; l++) {
        const int idx = tid + l * 256;   // 0..1023
        const int r = idx >> 3, c8 = idx & 7;
        CPA16(sb32 + (uint32_t)(AQP + r * HSTR + c8 * 8) * 2,
              qp + (size_t)(qb * 128 + r) * D_ + c8 * 8);
    }
    CP_COMMIT();
    CP_WAIT0();
    __syncthreads();

    // extract Q fragments via ldmatrix (own warp rows only)
    uint32_t qf[4][4];
    #pragma unroll
    for (int ks = 0; ks < 4; ks++)
        ldmx4(qf[ks], sb32 +
              (uint32_t)((AQP + (16 * w + l8 + arow) * HSTR) + ks * 16 + acol) * 2);

    float o[8][4];
    #pragma unroll
    for (int nf = 0; nf < 8; nf++)
        #pragma unroll
        for (int r = 0; r < 4; r++) o[nf][r] = 0.0f;

    float mA = -1e30f, mB = -1e30f, lA = 0.0f, lB = 0.0f;  // lA/lB per-lane partial
    const int rowA = qb * 128 + 16 * w + g;
    const int wrow_hi = qb * 128 + 16 * w + 15;
    const int sbmax = qb * 2 + 1;

    // prefetch K/V(1)
    attn_issue_kv(kp, vtp, sb32, 1, 1, tid);
    CP_COMMIT();

    for (int sb = 0; sb <= sbmax; sb++) {
        const int buf = sb & 1;
        if (sb > 0) {
            CP_WAIT0();
            __syncthreads();
            if (sb + 1 <= sbmax) {
                attn_issue_kv(kp, vtp, sb32, sb + 1, buf ^ 1, tid);
                CP_COMMIT();
            }
        }
        if (sb * 64 > wrow_hi) continue;   // fully-masked warp tile

        const uint32_t Ks32 = sb32 + (uint32_t)(AKS + buf * AKB) * 2;
        const uint32_t Vs32 = sb32 + (uint32_t)(AVS + buf * AVB) * 2;

        // ---- S = Q @ K^T ----
        float s[8][4];
        #pragma unroll
        for (int nf = 0; nf < 8; nf++)
            #pragma unroll
            for (int r = 0; r < 4; r++) s[nf][r] = 0.0f;

        #pragma unroll
        for (int ks = 0; ks < 4; ks++) {
            const int k0 = ks * 16;
            uint32_t b[4][4];
            #pragma unroll
            for (int p = 0; p < 4; p++)
                ldmx4(b[p], Ks32 +
                      (uint32_t)((p * 16 + l8 + brow) * HSTR + k0 + bcol) * 2);
            #pragma unroll
            for (int nf = 0; nf < 8; nf++)
                mma_fp16(s[nf], qf[ks], &b[nf >> 1][(nf & 1) * 2]);
        }

        // ---- causal mask ----
        if (sb * 64 + 63 > qb * 128 + 16 * w) {
            #pragma unroll
            for (int nf = 0; nf < 8; nf++) {
                const int c0 = sb * 64 + nf * 8 + 2 * t;
                if (c0 > rowA)     s[nf][0] = -1e30f;
                if (c0 + 1 > rowA) s[nf][1] = -1e30f;
                if (c0 > rowA + 8)     s[nf][2] = -1e30f;
                if (c0 + 1 > rowA + 8) s[nf][3] = -1e30f;
            }
        }

        // ---- online softmax (fp32, exp2 domain, deferred sum) ----
        float mxA = -1e30f, mxB = -1e30f;
        #pragma unroll
        for (int nf = 0; nf < 8; nf++) {
            mxA = fmaxf(mxA, fmaxf(s[nf][0], s[nf][1]));
            mxB = fmaxf(mxB, fmaxf(s[nf][2], s[nf][3]));
        }
        mxA = fmaxf(mxA, __shfl_xor_sync(0xFFFFFFFF, mxA, 1));
        mxA = fmaxf(mxA, __shfl_xor_sync(0xFFFFFFFF, mxA, 2));
        mxB = fmaxf(mxB, __shfl_xor_sync(0xFFFFFFFF, mxB, 1));
        mxB = fmaxf(mxB, __shfl_xor_sync(0xFFFFFFFF, mxB, 2));

        const float mnA = fmaxf(mA, mxA);
        const float mnB = fmaxf(mB, mxB);
        const float aA = exp2f(mA - mnA);
        const float aB = exp2f(mB - mnB);
        mA = mnA; mB = mnB;

        float suA = 0.0f, suB = 0.0f;    // per-lane partials (no shfl here)
        uint32_t p0h[8], p1h[8];
        #pragma unroll
        for (int nf = 0; nf < 8; nf++) {
            float p0 = exp2f(s[nf][0] - mnA);
            float p1 = exp2f(s[nf][1] - mnA);
            float p2 = exp2f(s[nf][2] - mnB);
            float p3 = exp2f(s[nf][3] - mnB);
            suA += p0 + p1; suB += p2 + p3;
            p0h[nf] = pack_h2(p0, p1);
            p1h[nf] = pack_h2(p2, p3);
        }
        lA = lA * aA + suA;
        lB = lB * aB + suB;

        #pragma unroll
        for (int nf = 0; nf < 8; nf++) {
            o[nf][0] *= aA; o[nf][1] *= aA;
            o[nf][2] *= aB; o[nf][3] *= aB;
        }

        // ---- P (fp16) to warp-private SMEM rows (Q region reuse) ----
        #pragma unroll
        for (int nf = 0; nf < 8; nf++) {
            *(uint32_t*)(sfh + AQP + (16 * w + g) * HSTR + nf * 8 + 2 * t) = p0h[nf];
            *(uint32_t*)(sfh + AQP + (16 * w + g + 8) * HSTR + nf * 8 + 2 * t) = p1h[nf];
        }
        __syncwarp();

        // ---- O += P @ V ----
        #pragma unroll
        for (int ks = 0; ks < 4; ks++) {
            const int k0 = ks * 16;
            uint32_t a[4];
            ldmx4(a, sb32 +
                  (uint32_t)((AQP + (16 * w + l8 + arow) * HSTR) + k0 + acol) * 2);
            uint32_t b[4][4];
            #pragma unroll
            for (int p = 0; p < 4; p++)
                ldmx4(b[p], Vs32 +
                      (uint32_t)((p * 16 + l8 + brow) * HSTR + k0 + bcol) * 2);
            #pragma unroll
            for (int nf = 0; nf < 8; nf++)
                mma_fp16(o[nf], a, &b[nf >> 1][(nf & 1) * 2]);
        }
        __syncwarp();   // P reads done before next iteration's P writes
    }

    // ---- epilogue: finish deferred l reduction, normalize, fp16 out ----
    lA += __shfl_xor_sync(0xFFFFFFFF, lA, 1);
    lA += __shfl_xor_sync(0xFFFFFFFF, lA, 2);
    lB += __shfl_xor_sync(0xFFFFFFFF, lB, 1);
    lB += __shfl_xor_sync(0xFFFFFFFF, lB, 2);

    const int b = bh >> 4, h = bh & 15;
    const float invA = 1.0f / lA;
    const float invB = 1.0f / lB;
    __half* dstA = g_att + ((size_t)(b * T_ + rowA)) * C_ + h * D_;
    __half* dstB = g_att + ((size_t)(b * T_ + rowA + 8)) * C_ + h * D_;
    #pragma unroll
    for (int nf = 0; nf < 8; nf++) {
        const int cc = nf * 8 + 2 * t;
        *(uint32_t*)(dstA + cc) = pack_h2(o[nf][0] * invA, o[nf][1] * invA);
        *(uint32_t*)(dstB + cc) = pack_h2(o[nf][2] * invB, o[nf][3] * invB);
    }
}

// ===========================================================================
extern "C" void kernel_launch(void* const* d_in, const int* in_sizes, int n_in,
                              void* d_out, int out_size)
{
    const float* x  = (const float*)d_in[0];
    const float* Wq = (const float*)d_in[1];
    const float* Wk = (const float*)d_in[2];
    const float* Wv = (const float*)d_in[3];
    const float* Wo = (const float*)d_in[4];
    const float* bo = (const float*)d_in[5];
    float* out = (float*)d_out;

    cudaFuncSetAttribute(attn_mma_kernel, cudaFuncAttributeMaxDynamicSharedMemorySize,
                         ATTN_SMEM_BYTES);
    cudaFuncSetAttribute(qkv_tc, cudaFuncAttributeMaxDynamicSharedMemorySize,
                         GEMM_SMEM_BYTES);
    cudaFuncSetAttribute(proj_tc, cudaFuncAttributeMaxDynamicSharedMemorySize,
                         GEMM_SMEM_BYTES);

    prep_all<<<8192, 256>>>(x, Wq, Wk, Wv, Wo);
    qkv_tc<<<dim3(64, 24), 256, GEMM_SMEM_BYTES>>>();
    attn_mma_kernel<<<dim3(T_ / 128, B_ * H_), 256, ATTN_SMEM_BYTES>>>();
    proj_tc<<<dim3(64, 8), 256, GEMM_SMEM_BYTES>>>(out, bo);
}

// round 14
// speedup vs baseline: 1.0113x; 1.0113x over previous
#include <cuda_runtime.h>
#include <cuda_fp16.h>
#include <math.h>
#include <cstdint>

// Problem constants
#define B_ 4
#define T_ 2048
#define C_ 1024
#define H_ 16
#define D_ 64
#define BT_ (B_ * T_)           // 8192

// Scratch (fp16 end-to-end; fp32 only in accumulators and final out)
__device__ __half g_q[B_ * H_ * T_ * D_];    // [B,H,T,D], pre-scaled by 0.125*log2e
__device__ __half g_k[B_ * H_ * T_ * D_];    // [B,H,T,D]
__device__ __half g_v[B_ * H_ * T_ * D_];    // [B,H,T,D]  (row-major; PV uses ldmatrix.trans)
__device__ __half g_att[B_ * T_ * C_];       // [B,T,H*D]
__device__ __half g_wt[3 * C_ * C_];         // K-major qkv weights [n=3072][k=1024]
__device__ __half g_wot[C_ * C_];            // K-major Wo [n=1024][k=1024]
__device__ __half g_xh[BT_ * C_];            // fp16 x

// Q pre-scale: (1/sqrt(64)) * log2(e), so softmax can use exp2 directly.
#define QSCALE 0.18033688011112042f

// ===========================================================================
// Helpers
// ===========================================================================
__device__ __forceinline__ void mma_fp16(float* c, const uint32_t* a, const uint32_t* b) {
    asm volatile(
        "mma.sync.aligned.m16n8k16.row.col.f32.f16.f16.f32 "
        "{%0,%1,%2,%3}, {%4,%5,%6,%7}, {%8,%9}, {%0,%1,%2,%3};\n"
        : "+f"(c[0]), "+f"(c[1]), "+f"(c[2]), "+f"(c[3])
        : "r"(a[0]), "r"(a[1]), "r"(a[2]), "r"(a[3]),
          "r"(b[0]), "r"(b[1]));
}

__device__ __forceinline__ void ldmx4(uint32_t* d, uint32_t addr) {
    asm volatile("ldmatrix.sync.aligned.m8n8.x4.shared.b16 {%0,%1,%2,%3}, [%4];"
        : "=r"(d[0]), "=r"(d[1]), "=r"(d[2]), "=r"(d[3]) : "r"(addr));
}

// Transposing variant: thread (g,t) receives M[2t..2t+1][g] of each 8x8 tile.
__device__ __forceinline__ void ldmx4t(uint32_t* d, uint32_t addr) {
    asm volatile("ldmatrix.sync.aligned.m8n8.x4.trans.shared.b16 {%0,%1,%2,%3}, [%4];"
        : "=r"(d[0]), "=r"(d[1]), "=r"(d[2]), "=r"(d[3]) : "r"(addr));
}

__device__ __forceinline__ uint32_t smem_u32(const void* p) {
    return (uint32_t)__cvta_generic_to_shared(p);
}

__device__ __forceinline__ uint32_t pack_h2(float lo, float hi) {
    __half2 h = __halves2half2(__float2half_rn(lo), __float2half_rn(hi));
    return *reinterpret_cast<uint32_t*>(&h);
}

#define CPA16(dst, src) \
    asm volatile("cp.async.ca.shared.global [%0], [%1], 16;" :: "r"(dst), "l"(src))
#define CP_COMMIT() asm volatile("cp.async.commit_group;" ::: "memory")
#define CP_WAIT0()  asm volatile("cp.async.wait_group 0;" ::: "memory")

extern __shared__ __align__(16) __half dyn_smh[];

// ===========================================================================
// Dense GEMM (fp16): 256 threads / 8 warps, warp tile 64x32 (2x4 layout),
// block 128x128x64.  2-stage cp.async; ldmatrix fragments.
// SMEM row stride 72 halves (row r starts at bank 4r%32 -> ldmatrix CF).
// ===========================================================================
#define HSTR 72
#define TILEH (128 * HSTR)                 // 9216 halves
#define BUFH  (2 * TILEH)                  // A+B per stage
#define GEMM_SMEM_BYTES (2 * BUFH * 2)     // 73728 bytes

__device__ __forceinline__ void gemm_issue_chunk(
    const __half* __restrict__ A0, const __half* __restrict__ B0,
    uint32_t sb32, int kc, int buf, int pr, int pc8)
{
    const uint32_t abase = sb32 + (uint32_t)(buf * BUFH) * 2;
    const uint32_t bbase = abase + (uint32_t)TILEH * 2;
    #pragma unroll
    for (int l = 0; l < 4; l++) {
        const int r = pr + l * 32;
        const uint32_t so = (uint32_t)(r * HSTR + pc8 * 8) * 2;
        CPA16(abase + so, A0 + (size_t)r * C_ + kc * 64 + pc8 * 8);
        CPA16(bbase + so, B0 + (size_t)r * C_ + kc * 64 + pc8 * 8);
    }
}

__device__ __forceinline__ void gemm_mainloop_fp16(
    const __half* __restrict__ A0, const __half* __restrict__ B0,
    float c[4][4][4])
{
    const int tid  = threadIdx.x;
    const int lane = tid & 31;
    const int wid  = tid >> 5;           // 0..7
    const int wm = (wid & 1) * 64;
    const int wn = (wid >> 1) * 32;
    const int l8 = lane & 7;
    const int mi = lane >> 3;            // ldmatrix sub-matrix index 0..3
    const int arow = (mi & 1) * 8;
    const int acol = (mi >> 1) * 8;
    const int brow = (mi >> 1) * 8;
    const int bcol = (mi & 1) * 8;
    const int pc8 = tid & 7;
    const int pr  = tid >> 3;            // 0..31

    const uint32_t sb32 = smem_u32(dyn_smh);

    #pragma unroll
    for (int mf = 0; mf < 4; mf++)
        #pragma unroll
        for (int nf = 0; nf < 4; nf++)
            #pragma unroll
            for (int r = 0; r < 4; r++) c[mf][nf][r] = 0.0f;

    gemm_issue_chunk(A0, B0, sb32, 0, 0, pr, pc8);
    CP_COMMIT();

    for (int kc = 0; kc < 16; kc++) {
        const int buf = kc & 1;
        CP_WAIT0();
        __syncthreads();
        if (kc < 15) {
            gemm_issue_chunk(A0, B0, sb32, kc + 1, buf ^ 1, pr, pc8);
            CP_COMMIT();
        }

        const uint32_t sA32 = sb32 + (uint32_t)(buf * BUFH) * 2;
        const uint32_t sB32 = sA32 + (uint32_t)TILEH * 2;

        #pragma unroll
        for (int ks = 0; ks < 4; ks++) {
            const int k0 = ks * 16;
            uint32_t a[4][4];
            #pragma unroll
            for (int mf = 0; mf < 4; mf++)
                ldmx4(a[mf], sA32 +
                      (uint32_t)((wm + mf * 16 + l8 + arow) * HSTR + k0 + acol) * 2);
            uint32_t b[2][4];
            #pragma unroll
            for (int p = 0; p < 2; p++)
                ldmx4(b[p], sB32 +
                      (uint32_t)((wn + p * 16 + l8 + brow) * HSTR + k0 + bcol) * 2);
            #pragma unroll
            for (int mf = 0; mf < 4; mf++)
                #pragma unroll
                for (int nf = 0; nf < 4; nf++)
                    mma_fp16(c[mf][nf], a[mf], &b[nf >> 1][(nf & 1) * 2]);
        }
    }
}

// ===========================================================================
// Merged prep kernel: convert x + transpose qkv weights + transpose Wo.
// ===========================================================================
__global__ __launch_bounds__(256) void prep_all(
    const float* __restrict__ x,
    const float* __restrict__ Wq, const float* __restrict__ Wk,
    const float* __restrict__ Wv, const float* __restrict__ Wo)
{
    __shared__ float tile[32][33];
    const int bid = blockIdx.x;

    if (bid < 4096) {
        const int base = (bid * 256 + threadIdx.x) * 8;
        float4 v0 = *(const float4*)(x + base);
        float4 v1 = *(const float4*)(x + base + 4);
        uint4 o;
        o.x = pack_h2(v0.x, v0.y);
        o.y = pack_h2(v0.z, v0.w);
        o.z = pack_h2(v1.x, v1.y);
        o.w = pack_h2(v1.z, v1.w);
        *(uint4*)(g_xh + base) = o;
        return;
    }

    const int tx = threadIdx.x & 31, ty = threadIdx.x >> 5;

    if (bid < 7168) {
        const int idx = bid - 4096;
        const int z = idx >> 6;
        const int rem = idx & 63;
        const int c0 = (rem & 31) * 32;
        const int d0 = (rem >> 5) * 32;
        const int which = z >> 4, h = z & 15;
        const float* W = (which == 0 ? Wq : (which == 1 ? Wk : Wv)) + (size_t)h * C_ * D_;

        #pragma unroll
        for (int i = 0; i < 4; i++)
            tile[ty + i * 8][tx] = W[(size_t)(c0 + ty + i * 8) * D_ + d0 + tx];
        __syncthreads();
        const int nbase = which * 1024 + h * 64 + d0;
        #pragma unroll
        for (int i = 0; i < 4; i++)
            g_wt[(size_t)(nbase + ty + i * 8) * C_ + c0 + tx] =
                __float2half_rn(tile[tx][ty + i * 8]);
    } else {
        const int idx = bid - 7168;
        const int c0 = (idx & 31) * 32;
        const int n0 = (idx >> 5) * 32;
        #pragma unroll
        for (int i = 0; i < 4; i++)
            tile[ty + i * 8][tx] = Wo[(size_t)(c0 + ty + i * 8) * C_ + n0 + tx];
        __syncthreads();
        #pragma unroll
        for (int i = 0; i < 4; i++)
            g_wot[(size_t)(n0 + ty + i * 8) * C_ + c0 + tx] =
                __float2half_rn(tile[tx][ty + i * 8]);
    }
}

// ===========================================================================
// Kernel 1: QKV projection (fp16).  grid (64, 24), 256 threads.
// q pre-scaled by QSCALE; q/k/v all written row-major (packed u32 stores).
// ===========================================================================
__global__ __launch_bounds__(256, 2) void qkv_tc()
{
    const int mt = blockIdx.x, nt = blockIdx.y;
    const __half* A0 = g_xh + (size_t)mt * 128 * C_;
    const __half* B0 = g_wt + (size_t)nt * 128 * C_;

    float c[4][4][4];
    gemm_mainloop_fp16(A0, B0, c);

    const int tid  = threadIdx.x;
    const int lane = tid & 31;
    const int wid  = tid >> 5;
    const int wm = (wid & 1) * 64;
    const int wn = (wid >> 1) * 32;
    const int g = lane >> 2;
    const int t4 = lane & 3;

    const int nb0 = nt * 128 + wn;
    const int which = nb0 >> 10;
    const int hh = (nb0 >> 6) & 15;
    const int dbase = nb0 & 63;          // 0 or 32 within the head

    const float sc = (which == 0) ? QSCALE : 1.0f;
    __half* outb = (which == 0) ? g_q : ((which == 1) ? g_k : g_v);

    #pragma unroll
    for (int mf = 0; mf < 4; mf++) {
        #pragma unroll
        for (int half = 0; half < 2; half++) {
            const int m = mt * 128 + wm + mf * 16 + g + half * 8;
            const int b = m >> 11, tt = m & (T_ - 1);
            __half* op = outb + ((size_t)(b * H_ + hh) * T_ + tt) * D_;
            #pragma unroll
            for (int nf = 0; nf < 4; nf++) {
                const int d = dbase + nf * 8 + t4 * 2;
                *(uint32_t*)(op + d) = pack_h2(c[mf][nf][half * 2] * sc,
                                               c[mf][nf][half * 2 + 1] * sc);
            }
        }
    }
}

// ===========================================================================
// Kernel 3: output projection + bias (fp16 in, fp32 out).  grid (64, 8).
// ===========================================================================
__global__ __launch_bounds__(256, 2) void proj_tc(float* __restrict__ out,
                                                  const float* __restrict__ bo)
{
    const int mt = blockIdx.x, nt = blockIdx.y;
    const __half* A0 = g_att + (size_t)mt * 128 * C_;
    const __half* B0 = g_wot + (size_t)nt * 128 * C_;

    float c[4][4][4];
    gemm_mainloop_fp16(A0, B0, c);

    const int tid  = threadIdx.x;
    const int lane = tid & 31;
    const int wid  = tid >> 5;
    const int wm = (wid & 1) * 64;
    const int wn = (wid >> 1) * 32;
    const int g = lane >> 2;
    const int t4 = lane & 3;

    #pragma unroll
    for (int mf = 0; mf < 4; mf++) {
        #pragma unroll
        for (int half = 0; half < 2; half++) {
            const int m = mt * 128 + wm + mf * 16 + g + half * 8;
            #pragma unroll
            for (int nf = 0; nf < 4; nf++) {
                const int n = nt * 128 + wn + nf * 8 + t4 * 2;
                float2 bv = *(const float2*)(bo + n);
                float2 v = make_float2(c[mf][nf][half * 2] + bv.x,
                                       c[mf][nf][half * 2 + 1] + bv.y);
                *(float2*)(out + (size_t)m * C_ + n) = v;
            }
        }
    }
}

// ===========================================================================
// Kernel 2: fp16 tensor-core causal flash attention.
// BQ=128, BS=64, 256 threads.  V row-major; PV B-fragments via ldmatrix.trans.
// Work-descending qb order; exp2-domain softmax; masked-tile skip; deferred l.
// ===========================================================================
#define AQP 0                        // Q then P: 128 x 72 halves
#define AKS (128 * HSTR)             // 9216
#define AKB (64 * HSTR)              // 4608
#define AVS (AKS + 2 * AKB)          // 18432
#define AVB (64 * HSTR)
#define ATTN_SMEM_BYTES ((AVS + 2 * AVB) * 2)   // 55296 bytes

__device__ __forceinline__ void attn_issue_kv(
    const __half* __restrict__ kp, const __half* __restrict__ vp,
    uint32_t sb32, int sb, int buf, int tid)
{
    const uint32_t kdst = sb32 + (uint32_t)(AKS + buf * AKB) * 2;
    const uint32_t vdst = sb32 + (uint32_t)(AVS + buf * AVB) * 2;
    #pragma unroll
    for (int l = 0; l < 2; l++) {
        const int idx = tid + l * 256;   // 0..511
        const int r = idx >> 3, c8 = idx & 7;
        CPA16(kdst + (uint32_t)(r * HSTR + c8 * 8) * 2,
              kp + (size_t)(sb * 64 + r) * D_ + c8 * 8);
        CPA16(vdst + (uint32_t)(r * HSTR + c8 * 8) * 2,
              vp + (size_t)(sb * 64 + r) * D_ + c8 * 8);
    }
}

__global__ __launch_bounds__(256, 2) void attn_mma_kernel()
{
    __half* sfh = dyn_smh;
    const int tid  = threadIdx.x;
    const int lane = tid & 31;
    const int w    = tid >> 5;
    const int g    = lane >> 2;
    const int t    = lane & 3;
    const int l8   = lane & 7;
    const int mi   = lane >> 3;
    const int arow = (mi & 1) * 8;       // A-role ldmatrix offsets
    const int acol = (mi >> 1) * 8;
    const int brow = (mi >> 1) * 8;      // B-role (non-trans, K) offsets
    const int bcol = (mi & 1) * 8;
    const int vrow = (mi & 1) * 8;       // B-role trans (V): row = s(k) dim
    const int vcol = (mi >> 1) * 8;      //                    col = d(n) dim
    const int qb   = (int)gridDim.x - 1 - (int)blockIdx.x;  // heavy blocks first
    const int bh   = blockIdx.y;

    const __half* qp = g_q + (size_t)bh * T_ * D_;
    const __half* kp = g_k + (size_t)bh * T_ * D_;
    const __half* vp = g_v + (size_t)bh * T_ * D_;
    const uint32_t sb32 = smem_u32(sfh);

    // stage Q (already QSCALE-scaled) + K/V(0) via cp.async
    attn_issue_kv(kp, vp, sb32, 0, 0, tid);
    #pragma unroll
    for (int l = 0; l < 4; l++) {
        const int idx = tid + l * 256;   // 0..1023
        const int r = idx >> 3, c8 = idx & 7;
        CPA16(sb32 + (uint32_t)(AQP + r * HSTR + c8 * 8) * 2,
              qp + (size_t)(qb * 128 + r) * D_ + c8 * 8);
    }
    CP_COMMIT();
    CP_WAIT0();
    __syncthreads();

    // extract Q fragments via ldmatrix (own warp rows only)
    uint32_t qf[4][4];
    #pragma unroll
    for (int ks = 0; ks < 4; ks++)
        ldmx4(qf[ks], sb32 +
              (uint32_t)((AQP + (16 * w + l8 + arow) * HSTR) + ks * 16 + acol) * 2);

    float o[8][4];
    #pragma unroll
    for (int nf = 0; nf < 8; nf++)
        #pragma unroll
        for (int r = 0; r < 4; r++) o[nf][r] = 0.0f;

    float mA = -1e30f, mB = -1e30f, lA = 0.0f, lB = 0.0f;  // per-lane partials
    const int rowA = qb * 128 + 16 * w + g;
    const int wrow_hi = qb * 128 + 16 * w + 15;
    const int sbmax = qb * 2 + 1;

    attn_issue_kv(kp, vp, sb32, 1, 1, tid);
    CP_COMMIT();

    for (int sb = 0; sb <= sbmax; sb++) {
        const int buf = sb & 1;
        if (sb > 0) {
            CP_WAIT0();
            __syncthreads();
            if (sb + 1 <= sbmax) {
                attn_issue_kv(kp, vp, sb32, sb + 1, buf ^ 1, tid);
                CP_COMMIT();
            }
        }
        if (sb * 64 > wrow_hi) continue;   // fully-masked warp tile

        const uint32_t Ks32 = sb32 + (uint32_t)(AKS + buf * AKB) * 2;
        const uint32_t Vs32 = sb32 + (uint32_t)(AVS + buf * AVB) * 2;

        // ---- S = Q @ K^T ----
        float s[8][4];
        #pragma unroll
        for (int nf = 0; nf < 8; nf++)
            #pragma unroll
            for (int r = 0; r < 4; r++) s[nf][r] = 0.0f;

        #pragma unroll
        for (int ks = 0; ks < 4; ks++) {
            const int k0 = ks * 16;
            uint32_t b[4][4];
            #pragma unroll
            for (int p = 0; p < 4; p++)
                ldmx4(b[p], Ks32 +
                      (uint32_t)((p * 16 + l8 + brow) * HSTR + k0 + bcol) * 2);
            #pragma unroll
            for (int nf = 0; nf < 8; nf++)
                mma_fp16(s[nf], qf[ks], &b[nf >> 1][(nf & 1) * 2]);
        }

        // ---- causal mask ----
        if (sb * 64 + 63 > qb * 128 + 16 * w) {
            #pragma unroll
            for (int nf = 0; nf < 8; nf++) {
                const int c0 = sb * 64 + nf * 8 + 2 * t;
                if (c0 > rowA)     s[nf][0] = -1e30f;
                if (c0 + 1 > rowA) s[nf][1] = -1e30f;
                if (c0 > rowA + 8)     s[nf][2] = -1e30f;
                if (c0 + 1 > rowA + 8) s[nf][3] = -1e30f;
            }
        }

        // ---- online softmax (fp32, exp2 domain, deferred sum) ----
        float mxA = -1e30f, mxB = -1e30f;
        #pragma unroll
        for (int nf = 0; nf < 8; nf++) {
            mxA = fmaxf(mxA, fmaxf(s[nf][0], s[nf][1]));
            mxB = fmaxf(mxB, fmaxf(s[nf][2], s[nf][3]));
        }
        mxA = fmaxf(mxA, __shfl_xor_sync(0xFFFFFFFF, mxA, 1));
        mxA = fmaxf(mxA, __shfl_xor_sync(0xFFFFFFFF, mxA, 2));
        mxB = fmaxf(mxB, __shfl_xor_sync(0xFFFFFFFF, mxB, 1));
        mxB = fmaxf(mxB, __shfl_xor_sync(0xFFFFFFFF, mxB, 2));

        const float mnA = fmaxf(mA, mxA);
        const float mnB = fmaxf(mB, mxB);
        const float aA = exp2f(mA - mnA);
        const float aB = exp2f(mB - mnB);
        mA = mnA; mB = mnB;

        float suA = 0.0f, suB = 0.0f;
        uint32_t p0h[8], p1h[8];
        #pragma unroll
        for (int nf = 0; nf < 8; nf++) {
            float p0 = exp2f(s[nf][0] - mnA);
            float p1 = exp2f(s[nf][1] - mnA);
            float p2 = exp2f(s[nf][2] - mnB);
            float p3 = exp2f(s[nf][3] - mnB);
            suA += p0 + p1; suB += p2 + p3;
            p0h[nf] = pack_h2(p0, p1);
            p1h[nf] = pack_h2(p2, p3);
        }
        lA = lA * aA + suA;
        lB = lB * aB + suB;

        #pragma unroll
        for (int nf = 0; nf < 8; nf++) {
            o[nf][0] *= aA; o[nf][1] *= aA;
            o[nf][2] *= aB; o[nf][3] *= aB;
        }

        // ---- P (fp16) to warp-private SMEM rows (Q region reuse) ----
        #pragma unroll
        for (int nf = 0; nf < 8; nf++) {
            *(uint32_t*)(sfh + AQP + (16 * w + g) * HSTR + nf * 8 + 2 * t) = p0h[nf];
            *(uint32_t*)(sfh + AQP + (16 * w + g + 8) * HSTR + nf * 8 + 2 * t) = p1h[nf];
        }
        __syncwarp();

        // ---- O += P @ V  (V row-major; B-fragments via trans-ldmatrix) ----
        #pragma unroll
        for (int ks = 0; ks < 4; ks++) {
            const int k0 = ks * 16;
            uint32_t a[4];
            ldmx4(a, sb32 +
                  (uint32_t)((AQP + (16 * w + l8 + arow) * HSTR) + k0 + acol) * 2);
            uint32_t b[4][4];
            #pragma unroll
            for (int p = 0; p < 4; p++)
                ldmx4t(b[p], Vs32 +
                       (uint32_t)((k0 + l8 + vrow) * HSTR + p * 16 + vcol) * 2);
            #pragma unroll
            for (int nf = 0; nf < 8; nf++)
                mma_fp16(o[nf], a, &b[nf >> 1][(nf & 1) * 2]);
        }
        __syncwarp();   // P reads done before next iteration's P writes
    }

    // ---- epilogue: finish deferred l reduction, normalize, fp16 out ----
    lA += __shfl_xor_sync(0xFFFFFFFF, lA, 1);
    lA += __shfl_xor_sync(0xFFFFFFFF, lA, 2);
    lB += __shfl_xor_sync(0xFFFFFFFF, lB, 1);
    lB += __shfl_xor_sync(0xFFFFFFFF, lB, 2);

    const int b = bh >> 4, h = bh & 15;
    const float invA = 1.0f / lA;
    const float invB = 1.0f / lB;
    __half* dstA = g_att + ((size_t)(b * T_ + rowA)) * C_ + h * D_;
    __half* dstB = g_att + ((size_t)(b * T_ + rowA + 8)) * C_ + h * D_;
    #pragma unroll
    for (int nf = 0; nf < 8; nf++) {
        const int cc = nf * 8 + 2 * t;
        *(uint32_t*)(dstA + cc) = pack_h2(o[nf][0] * invA, o[nf][1] * invA);
        *(uint32_t*)(dstB + cc) = pack_h2(o[nf][2] * invB, o[nf][3] * invB);
    }
}

// ===========================================================================
extern "C" void kernel_launch(void* const* d_in, const int* in_sizes, int n_in,
                              void* d_out, int out_size)
{
    const float* x  = (const float*)d_in[0];
    const float* Wq = (const float*)d_in[1];
    const float* Wk = (const float*)d_in[2];
    const float* Wv = (const float*)d_in[3];
    const float* Wo = (const float*)d_in[4];
    const float* bo = (const float*)d_in[5];
    float* out = (float*)d_out;

    cudaFuncSetAttribute(attn_mma_kernel, cudaFuncAttributeMaxDynamicSharedMemorySize,
                         ATTN_SMEM_BYTES);
    cudaFuncSetAttribute(qkv_tc, cudaFuncAttributeMaxDynamicSharedMemorySize,
                         GEMM_SMEM_BYTES);
    cudaFuncSetAttribute(proj_tc, cudaFuncAttributeMaxDynamicSharedMemorySize,
                         GEMM_SMEM_BYTES);

    prep_all<<<8192, 256>>>(x, Wq, Wk, Wv, Wo);
    qkv_tc<<<dim3(64, 24), 256, GEMM_SMEM_BYTES>>>();
    attn_mma_kernel<<<dim3(T_ / 128, B_ * H_), 256, ATTN_SMEM_BYTES>>>();
    proj_tc<<<dim3(64, 8), 256, GEMM_SMEM_BYTES>>>(out, bo);
}

// round 15
// speedup vs baseline: 1.0406x; 1.0290x over previous
#include <cuda_runtime.h>
#include <cuda_fp16.h>
#include <math.h>
#include <cstdint>

// Problem constants
#define B_ 4
#define T_ 2048
#define C_ 1024
#define H_ 16
#define D_ 64
#define BT_ (B_ * T_)           // 8192

// Scratch (fp16 end-to-end; fp32 only in accumulators and final out)
__device__ __half g_q[B_ * H_ * T_ * D_];    // [B,H,T,D], pre-scaled by 0.125*log2e
__device__ __half g_k[B_ * H_ * T_ * D_];    // [B,H,T,D]
__device__ __half g_v[B_ * H_ * T_ * D_];    // [B,H,T,D]  (row-major; PV uses ldmatrix.trans)
__device__ __half g_att[B_ * T_ * C_];       // [B,T,H*D]
__device__ __half g_wt[3 * C_ * C_];         // K-major qkv weights [n=3072][k=1024]
__device__ __half g_wot[C_ * C_];            // K-major Wo [n=1024][k=1024]
__device__ __half g_xh[BT_ * C_];            // fp16 x

// Q pre-scale: (1/sqrt(64)) * log2(e), so softmax can use exp2 directly.
#define QSCALE 0.18033688011112042f

// ===========================================================================
// Helpers
// ===========================================================================
__device__ __forceinline__ void mma_fp16(float* c, const uint32_t* a, const uint32_t* b) {
    asm volatile(
        "mma.sync.aligned.m16n8k16.row.col.f32.f16.f16.f32 "
        "{%0,%1,%2,%3}, {%4,%5,%6,%7}, {%8,%9}, {%0,%1,%2,%3};\n"
        : "+f"(c[0]), "+f"(c[1]), "+f"(c[2]), "+f"(c[3])
        : "r"(a[0]), "r"(a[1]), "r"(a[2]), "r"(a[3]),
          "r"(b[0]), "r"(b[1]));
}

__device__ __forceinline__ void ldmx4(uint32_t* d, uint32_t addr) {
    asm volatile("ldmatrix.sync.aligned.m8n8.x4.shared.b16 {%0,%1,%2,%3}, [%4];"
        : "=r"(d[0]), "=r"(d[1]), "=r"(d[2]), "=r"(d[3]) : "r"(addr));
}

// Transposing variant: thread (g,t) receives M[2t..2t+1][g] of each 8x8 tile.
__device__ __forceinline__ void ldmx4t(uint32_t* d, uint32_t addr) {
    asm volatile("ldmatrix.sync.aligned.m8n8.x4.trans.shared.b16 {%0,%1,%2,%3}, [%4];"
        : "=r"(d[0]), "=r"(d[1]), "=r"(d[2]), "=r"(d[3]) : "r"(addr));
}

__device__ __forceinline__ uint32_t smem_u32(const void* p) {
    return (uint32_t)__cvta_generic_to_shared(p);
}

__device__ __forceinline__ uint32_t pack_h2(float lo, float hi) {
    __half2 h = __halves2half2(__float2half_rn(lo), __float2half_rn(hi));
    return *reinterpret_cast<uint32_t*>(&h);
}

#define CPA16(dst, src) \
    asm volatile("cp.async.ca.shared.global [%0], [%1], 16;" :: "r"(dst), "l"(src))
#define CP_COMMIT() asm volatile("cp.async.commit_group;" ::: "memory")
#define CP_WAIT0()  asm volatile("cp.async.wait_group 0;" ::: "memory")

extern __shared__ __align__(16) __half dyn_smh[];

// ===========================================================================
// Dense GEMM (fp16): 256 threads / 8 warps, warp tile 64x32 (2x4 layout),
// block 128x128x64.  2-stage cp.async; ldmatrix fragments.
// SMEM row stride 72 halves (row r starts at bank 4r%32 -> ldmatrix CF).
// ===========================================================================
#define HSTR 72
#define TILEH (128 * HSTR)                 // 9216 halves
#define BUFH  (2 * TILEH)                  // A+B per stage
#define GEMM_SMEM_BYTES (2 * BUFH * 2)     // 73728 bytes

__device__ __forceinline__ void gemm_issue_chunk(
    const __half* __restrict__ A0, const __half* __restrict__ B0,
    uint32_t sb32, int kc, int buf, int pr, int pc8)
{
    const uint32_t abase = sb32 + (uint32_t)(buf * BUFH) * 2;
    const uint32_t bbase = abase + (uint32_t)TILEH * 2;
    #pragma unroll
    for (int l = 0; l < 4; l++) {
        const int r = pr + l * 32;
        const uint32_t so = (uint32_t)(r * HSTR + pc8 * 8) * 2;
        CPA16(abase + so, A0 + (size_t)r * C_ + kc * 64 + pc8 * 8);
        CPA16(bbase + so, B0 + (size_t)r * C_ + kc * 64 + pc8 * 8);
    }
}

__device__ __forceinline__ void gemm_mainloop_fp16(
    const __half* __restrict__ A0, const __half* __restrict__ B0,
    float c[4][4][4])
{
    const int tid  = threadIdx.x;
    const int lane = tid & 31;
    const int wid  = tid >> 5;           // 0..7
    const int wm = (wid & 1) * 64;
    const int wn = (wid >> 1) * 32;
    const int l8 = lane & 7;
    const int mi = lane >> 3;            // ldmatrix sub-matrix index 0..3
    const int arow = (mi & 1) * 8;
    const int acol = (mi >> 1) * 8;
    const int brow = (mi >> 1) * 8;
    const int bcol = (mi & 1) * 8;
    const int pc8 = tid & 7;
    const int pr  = tid >> 3;            // 0..31

    const uint32_t sb32 = smem_u32(dyn_smh);

    #pragma unroll
    for (int mf = 0; mf < 4; mf++)
        #pragma unroll
        for (int nf = 0; nf < 4; nf++)
            #pragma unroll
            for (int r = 0; r < 4; r++) c[mf][nf][r] = 0.0f;

    gemm_issue_chunk(A0, B0, sb32, 0, 0, pr, pc8);
    CP_COMMIT();

    for (int kc = 0; kc < 16; kc++) {
        const int buf = kc & 1;
        CP_WAIT0();
        __syncthreads();
        if (kc < 15) {
            gemm_issue_chunk(A0, B0, sb32, kc + 1, buf ^ 1, pr, pc8);
            CP_COMMIT();
        }

        const uint32_t sA32 = sb32 + (uint32_t)(buf * BUFH) * 2;
        const uint32_t sB32 = sA32 + (uint32_t)TILEH * 2;

        #pragma unroll
        for (int ks = 0; ks < 4; ks++) {
            const int k0 = ks * 16;
            uint32_t a[4][4];
            #pragma unroll
            for (int mf = 0; mf < 4; mf++)
                ldmx4(a[mf], sA32 +
                      (uint32_t)((wm + mf * 16 + l8 + arow) * HSTR + k0 + acol) * 2);
            uint32_t b[2][4];
            #pragma unroll
            for (int p = 0; p < 2; p++)
                ldmx4(b[p], sB32 +
                      (uint32_t)((wn + p * 16 + l8 + brow) * HSTR + k0 + bcol) * 2);
            #pragma unroll
            for (int mf = 0; mf < 4; mf++)
                #pragma unroll
                for (int nf = 0; nf < 4; nf++)
                    mma_fp16(c[mf][nf], a[mf], &b[nf >> 1][(nf & 1) * 2]);
        }
    }
}

// ===========================================================================
// Merged prep kernel: convert x + transpose qkv weights + transpose Wo.
// ===========================================================================
__global__ __launch_bounds__(256) void prep_all(
    const float* __restrict__ x,
    const float* __restrict__ Wq, const float* __restrict__ Wk,
    const float* __restrict__ Wv, const float* __restrict__ Wo)
{
    __shared__ float tile[32][33];
    const int bid = blockIdx.x;

    if (bid < 4096) {
        const int base = (bid * 256 + threadIdx.x) * 8;
        float4 v0 = *(const float4*)(x + base);
        float4 v1 = *(const float4*)(x + base + 4);
        uint4 o;
        o.x = pack_h2(v0.x, v0.y);
        o.y = pack_h2(v0.z, v0.w);
        o.z = pack_h2(v1.x, v1.y);
        o.w = pack_h2(v1.z, v1.w);
        *(uint4*)(g_xh + base) = o;
        return;
    }

    const int tx = threadIdx.x & 31, ty = threadIdx.x >> 5;

    if (bid < 7168) {
        const int idx = bid - 4096;
        const int z = idx >> 6;
        const int rem = idx & 63;
        const int c0 = (rem & 31) * 32;
        const int d0 = (rem >> 5) * 32;
        const int which = z >> 4, h = z & 15;
        const float* W = (which == 0 ? Wq : (which == 1 ? Wk : Wv)) + (size_t)h * C_ * D_;

        #pragma unroll
        for (int i = 0; i < 4; i++)
            tile[ty + i * 8][tx] = W[(size_t)(c0 + ty + i * 8) * D_ + d0 + tx];
        __syncthreads();
        const int nbase = which * 1024 + h * 64 + d0;
        #pragma unroll
        for (int i = 0; i < 4; i++)
            g_wt[(size_t)(nbase + ty + i * 8) * C_ + c0 + tx] =
                __float2half_rn(tile[tx][ty + i * 8]);
    } else {
        const int idx = bid - 7168;
        const int c0 = (idx & 31) * 32;
        const int n0 = (idx >> 5) * 32;
        #pragma unroll
        for (int i = 0; i < 4; i++)
            tile[ty + i * 8][tx] = Wo[(size_t)(c0 + ty + i * 8) * C_ + n0 + tx];
        __syncthreads();
        #pragma unroll
        for (int i = 0; i < 4; i++)
            g_wot[(size_t)(n0 + ty + i * 8) * C_ + c0 + tx] =
                __float2half_rn(tile[tx][ty + i * 8]);
    }
}

// ===========================================================================
// Kernel 1: QKV projection (fp16).  grid (64, 24), 256 threads.
// ===========================================================================
__global__ __launch_bounds__(256, 2) void qkv_tc()
{
    const int mt = blockIdx.x, nt = blockIdx.y;
    const __half* A0 = g_xh + (size_t)mt * 128 * C_;
    const __half* B0 = g_wt + (size_t)nt * 128 * C_;

    float c[4][4][4];
    gemm_mainloop_fp16(A0, B0, c);

    const int tid  = threadIdx.x;
    const int lane = tid & 31;
    const int wid  = tid >> 5;
    const int wm = (wid & 1) * 64;
    const int wn = (wid >> 1) * 32;
    const int g = lane >> 2;
    const int t4 = lane & 3;

    const int nb0 = nt * 128 + wn;
    const int which = nb0 >> 10;
    const int hh = (nb0 >> 6) & 15;
    const int dbase = nb0 & 63;          // 0 or 32 within the head

    const float sc = (which == 0) ? QSCALE : 1.0f;
    __half* outb = (which == 0) ? g_q : ((which == 1) ? g_k : g_v);

    #pragma unroll
    for (int mf = 0; mf < 4; mf++) {
        #pragma unroll
        for (int half = 0; half < 2; half++) {
            const int m = mt * 128 + wm + mf * 16 + g + half * 8;
            const int b = m >> 11, tt = m & (T_ - 1);
            __half* op = outb + ((size_t)(b * H_ + hh) * T_ + tt) * D_;
            #pragma unroll
            for (int nf = 0; nf < 4; nf++) {
                const int d = dbase + nf * 8 + t4 * 2;
                *(uint32_t*)(op + d) = pack_h2(c[mf][nf][half * 2] * sc,
                                               c[mf][nf][half * 2 + 1] * sc);
            }
        }
    }
}

// ===========================================================================
// Kernel 3: output projection + bias (fp16 in, fp32 out).  grid (64, 8).
// ===========================================================================
__global__ __launch_bounds__(256, 2) void proj_tc(float* __restrict__ out,
                                                  const float* __restrict__ bo)
{
    const int mt = blockIdx.x, nt = blockIdx.y;
    const __half* A0 = g_att + (size_t)mt * 128 * C_;
    const __half* B0 = g_wot + (size_t)nt * 128 * C_;

    float c[4][4][4];
    gemm_mainloop_fp16(A0, B0, c);

    const int tid  = threadIdx.x;
    const int lane = tid & 31;
    const int wid  = tid >> 5;
    const int wm = (wid & 1) * 64;
    const int wn = (wid >> 1) * 32;
    const int g = lane >> 2;
    const int t4 = lane & 3;

    #pragma unroll
    for (int mf = 0; mf < 4; mf++) {
        #pragma unroll
        for (int half = 0; half < 2; half++) {
            const int m = mt * 128 + wm + mf * 16 + g + half * 8;
            #pragma unroll
            for (int nf = 0; nf < 4; nf++) {
                const int n = nt * 128 + wn + nf * 8 + t4 * 2;
                float2 bv = *(const float2*)(bo + n);
                float2 v = make_float2(c[mf][nf][half * 2] + bv.x,
                                       c[mf][nf][half * 2 + 1] + bv.y);
                *(float2*)(out + (size_t)m * C_ + n) = v;
            }
        }
    }
}

// ===========================================================================
// Kernel 2: fp16 tensor-core causal flash attention.
// BQ=128, BS=64, 256 threads.  P stays in registers: the fp16 C-fragment
// layout of S IS the A-fragment layout of PV (p0h/p1h pairs), so there is
// no P SMEM round-trip at all.  V row-major, B-fragments via ldmatrix.trans.
// ===========================================================================
#define AQP 0                        // Q staging: 128 x 72 halves
#define AKS (128 * HSTR)             // 9216
#define AKB (64 * HSTR)              // 4608
#define AVS (AKS + 2 * AKB)          // 18432
#define AVB (64 * HSTR)
#define ATTN_SMEM_BYTES ((AVS + 2 * AVB) * 2)   // 55296 bytes

__device__ __forceinline__ void attn_issue_kv(
    const __half* __restrict__ kp, const __half* __restrict__ vp,
    uint32_t sb32, int sb, int buf, int tid)
{
    const uint32_t kdst = sb32 + (uint32_t)(AKS + buf * AKB) * 2;
    const uint32_t vdst = sb32 + (uint32_t)(AVS + buf * AVB) * 2;
    #pragma unroll
    for (int l = 0; l < 2; l++) {
        const int idx = tid + l * 256;   // 0..511
        const int r = idx >> 3, c8 = idx & 7;
        CPA16(kdst + (uint32_t)(r * HSTR + c8 * 8) * 2,
              kp + (size_t)(sb * 64 + r) * D_ + c8 * 8);
        CPA16(vdst + (uint32_t)(r * HSTR + c8 * 8) * 2,
              vp + (size_t)(sb * 64 + r) * D_ + c8 * 8);
    }
}

__global__ __launch_bounds__(256, 2) void attn_mma_kernel()
{
    __half* sfh = dyn_smh;
    const int tid  = threadIdx.x;
    const int lane = tid & 31;
    const int w    = tid >> 5;
    const int g    = lane >> 2;
    const int t    = lane & 3;
    const int l8   = lane & 7;
    const int mi   = lane >> 3;
    const int arow = (mi & 1) * 8;       // A-role ldmatrix offsets
    const int acol = (mi >> 1) * 8;
    const int brow = (mi >> 1) * 8;      // B-role (non-trans, K) offsets
    const int bcol = (mi & 1) * 8;
    const int vrow = (mi & 1) * 8;       // B-role trans (V): row = s(k) dim
    const int vcol = (mi >> 1) * 8;      //                    col = d(n) dim
    const int qb   = (int)gridDim.x - 1 - (int)blockIdx.x;  // heavy blocks first
    const int bh   = blockIdx.y;

    const __half* qp = g_q + (size_t)bh * T_ * D_;
    const __half* kp = g_k + (size_t)bh * T_ * D_;
    const __half* vp = g_v + (size_t)bh * T_ * D_;
    const uint32_t sb32 = smem_u32(sfh);

    // stage Q (already QSCALE-scaled) + K/V(0) via cp.async
    attn_issue_kv(kp, vp, sb32, 0, 0, tid);
    #pragma unroll
    for (int l = 0; l < 4; l++) {
        const int idx = tid + l * 256;   // 0..1023
        const int r = idx >> 3, c8 = idx & 7;
        CPA16(sb32 + (uint32_t)(AQP + r * HSTR + c8 * 8) * 2,
              qp + (size_t)(qb * 128 + r) * D_ + c8 * 8);
    }
    CP_COMMIT();
    CP_WAIT0();
    __syncthreads();

    // extract Q fragments via ldmatrix (own warp rows only)
    uint32_t qf[4][4];
    #pragma unroll
    for (int ks = 0; ks < 4; ks++)
        ldmx4(qf[ks], sb32 +
              (uint32_t)((AQP + (16 * w + l8 + arow) * HSTR) + ks * 16 + acol) * 2);

    float o[8][4];
    #pragma unroll
    for (int nf = 0; nf < 8; nf++)
        #pragma unroll
        for (int r = 0; r < 4; r++) o[nf][r] = 0.0f;

    float mA = -1e30f, mB = -1e30f, lA = 0.0f, lB = 0.0f;  // per-lane partials
    const int rowA = qb * 128 + 16 * w + g;
    const int wrow_hi = qb * 128 + 16 * w + 15;
    const int sbmax = qb * 2 + 1;

    attn_issue_kv(kp, vp, sb32, 1, 1, tid);
    CP_COMMIT();

    for (int sb = 0; sb <= sbmax; sb++) {
        const int buf = sb & 1;
        if (sb > 0) {
            CP_WAIT0();
            __syncthreads();
            if (sb + 1 <= sbmax) {
                attn_issue_kv(kp, vp, sb32, sb + 1, buf ^ 1, tid);
                CP_COMMIT();
            }
        }
        if (sb * 64 > wrow_hi) continue;   // fully-masked warp tile

        const uint32_t Ks32 = sb32 + (uint32_t)(AKS + buf * AKB) * 2;
        const uint32_t Vs32 = sb32 + (uint32_t)(AVS + buf * AVB) * 2;

        // ---- S = Q @ K^T ----
        float s[8][4];
        #pragma unroll
        for (int nf = 0; nf < 8; nf++)
            #pragma unroll
            for (int r = 0; r < 4; r++) s[nf][r] = 0.0f;

        #pragma unroll
        for (int ks = 0; ks < 4; ks++) {
            const int k0 = ks * 16;
            uint32_t b[4][4];
            #pragma unroll
            for (int p = 0; p < 4; p++)
                ldmx4(b[p], Ks32 +
                      (uint32_t)((p * 16 + l8 + brow) * HSTR + k0 + bcol) * 2);
            #pragma unroll
            for (int nf = 0; nf < 8; nf++)
                mma_fp16(s[nf], qf[ks], &b[nf >> 1][(nf & 1) * 2]);
        }

        // ---- causal mask ----
        if (sb * 64 + 63 > qb * 128 + 16 * w) {
            #pragma unroll
            for (int nf = 0; nf < 8; nf++) {
                const int c0 = sb * 64 + nf * 8 + 2 * t;
                if (c0 > rowA)     s[nf][0] = -1e30f;
                if (c0 + 1 > rowA) s[nf][1] = -1e30f;
                if (c0 > rowA + 8)     s[nf][2] = -1e30f;
                if (c0 + 1 > rowA + 8) s[nf][3] = -1e30f;
            }
        }

        // ---- online softmax (fp32, exp2 domain, deferred sum) ----
        float mxA = -1e30f, mxB = -1e30f;
        #pragma unroll
        for (int nf = 0; nf < 8; nf++) {
            mxA = fmaxf(mxA, fmaxf(s[nf][0], s[nf][1]));
            mxB = fmaxf(mxB, fmaxf(s[nf][2], s[nf][3]));
        }
        mxA = fmaxf(mxA, __shfl_xor_sync(0xFFFFFFFF, mxA, 1));
        mxA = fmaxf(mxA, __shfl_xor_sync(0xFFFFFFFF, mxA, 2));
        mxB = fmaxf(mxB, __shfl_xor_sync(0xFFFFFFFF, mxB, 1));
        mxB = fmaxf(mxB, __shfl_xor_sync(0xFFFFFFFF, mxB, 2));

        const float mnA = fmaxf(mA, mxA);
        const float mnB = fmaxf(mB, mxB);
        const float aA = exp2f(mA - mnA);
        const float aB = exp2f(mB - mnB);
        mA = mnA; mB = mnB;

        // P stays in registers: p0h[nf]/p1h[nf] are EXACTLY the PV A-fragment
        // register pairs (rows g / g+8, cols 8nf+2t..+1).
        float suA = 0.0f, suB = 0.0f;
        uint32_t p0h[8], p1h[8];
        #pragma unroll
        for (int nf = 0; nf < 8; nf++) {
            float p0 = exp2f(s[nf][0] - mnA);
            float p1 = exp2f(s[nf][1] - mnA);
            float p2 = exp2f(s[nf][2] - mnB);
            float p3 = exp2f(s[nf][3] - mnB);
            suA += p0 + p1; suB += p2 + p3;
            p0h[nf] = pack_h2(p0, p1);
            p1h[nf] = pack_h2(p2, p3);
        }
        lA = lA * aA + suA;
        lB = lB * aB + suB;

        #pragma unroll
        for (int nf = 0; nf < 8; nf++) {
            o[nf][0] *= aA; o[nf][1] *= aA;
            o[nf][2] *= aB; o[nf][3] *= aB;
        }

        // ---- O += P @ V  (A from registers; B via trans-ldmatrix on V) ----
        #pragma unroll
        for (int ks = 0; ks < 4; ks++) {
            const int k0 = ks * 16;
            uint32_t a[4] = { p0h[2 * ks], p1h[2 * ks],
                              p0h[2 * ks + 1], p1h[2 * ks + 1] };
            uint32_t b[4][4];
            #pragma unroll
            for (int p = 0; p < 4; p++)
                ldmx4t(b[p], Vs32 +
                       (uint32_t)((k0 + l8 + vrow) * HSTR + p * 16 + vcol) * 2);
            #pragma unroll
            for (int nf = 0; nf < 8; nf++)
                mma_fp16(o[nf], a, &b[nf >> 1][(nf & 1) * 2]);
        }
    }

    // ---- epilogue: finish deferred l reduction, normalize, fp16 out ----
    lA += __shfl_xor_sync(0xFFFFFFFF, lA, 1);
    lA += __shfl_xor_sync(0xFFFFFFFF, lA, 2);
    lB += __shfl_xor_sync(0xFFFFFFFF, lB, 1);
    lB += __shfl_xor_sync(0xFFFFFFFF, lB, 2);

    const int b = bh >> 4, h = bh & 15;
    const float invA = 1.0f / lA;
    const float invB = 1.0f / lB;
    __half* dstA = g_att + ((size_t)(b * T_ + rowA)) * C_ + h * D_;
    __half* dstB = g_att + ((size_t)(b * T_ + rowA + 8)) * C_ + h * D_;
    #pragma unroll
    for (int nf = 0; nf < 8; nf++) {
        const int cc = nf * 8 + 2 * t;
        *(uint32_t*)(dstA + cc) = pack_h2(o[nf][0] * invA, o[nf][1] * invA);
        *(uint32_t*)(dstB + cc) = pack_h2(o[nf][2] * invB, o[nf][3] * invB);
    }
}

// ===========================================================================
extern "C" void kernel_launch(void* const* d_in, const int* in_sizes, int n_in,
                              void* d_out, int out_size)
{
    const float* x  = (const float*)d_in[0];
    const float* Wq = (const float*)d_in[1];
    const float* Wk = (const float*)d_in[2];
    const float* Wv = (const float*)d_in[3];
    const float* Wo = (const float*)d_in[4];
    const float* bo = (const float*)d_in[5];
    float* out = (float*)d_out;

    cudaFuncSetAttribute(attn_mma_kernel, cudaFuncAttributeMaxDynamicSharedMemorySize,
                         ATTN_SMEM_BYTES);
    cudaFuncSetAttribute(qkv_tc, cudaFuncAttributeMaxDynamicSharedMemorySize,
                         GEMM_SMEM_BYTES);
    cudaFuncSetAttribute(proj_tc, cudaFuncAttributeMaxDynamicSharedMemorySize,
                         GEMM_SMEM_BYTES);

    prep_all<<<8192, 256>>>(x, Wq, Wk, Wv, Wo);
    qkv_tc<<<dim3(64, 24), 256, GEMM_SMEM_BYTES>>>();
    attn_mma_kernel<<<dim3(T_ / 128, B_ * H_), 256, ATTN_SMEM_BYTES>>>();
    proj_tc<<<dim3(64, 8), 256, GEMM_SMEM_BYTES>>>(out, bo);
}